// round 14
// baseline (speedup 1.0000x reference)
#include <cuda_runtime.h>
#include <cuda_bf16.h>
#include <cstdint>

// ---------------- constants ----------------
#define B_   32
#define T_   4096
#define CIN_ 8
#define CR_  64
#define CS_  256
#define L_   20
#define TT_  256               // skip-kernel tile
#define TTL  128               // layer-kernel tile
#define NTPC 4                 // tiles per persistent layer CTA
#define HSZ  (B_ * CR_ * T_)

#if defined(__CUDA_ARCH_FEAT_SM103_ALL) || defined(__CUDA_ARCH_FEAT_SM100_ALL) || defined(__CUDA_ARCH_SPECIFIC__)
#define HAS_TC 1
#else
#define HAS_TC 0
#endif

typedef unsigned long long u64;

__device__ float g_h0[HSZ];
__device__ float g_h1[HSZ];
// fallback (scalar) path: fp32 z
__device__ float g_z[(size_t)L_ * HSZ];
// tc path: z as SW128 [t(256)][cin] bf16 tile images: [layer][skiptile(512)][hi 32KB | lo 32KB]
__device__ unsigned char g_zsw[(size_t)L_ * 512 * 65536];
// pre-converted weights (tile images, SW128, bf16 hi/lo)
__device__ unsigned char g_wfgp[(size_t)L_ * 65536];  // WP_H|WP_L|WC_H|WC_L (16KB each)
__device__ unsigned char g_wrp [(size_t)L_ * 16384];  // WR_H|WR_L (8KB each)
__device__ unsigned char g_wsp [(size_t)L_ * 65536];  // Ah0|Al0|Ah1|Al1 (16KB each)

// ---------------- f32x2 helpers (scalar fallback) ----------------
__device__ __forceinline__ u64 fma2(u64 a, u64 b, u64 c) {
    u64 d;
    asm("fma.rn.f32x2 %0,%1,%2,%3;" : "=l"(d) : "l"(a), "l"(b), "l"(c));
    return d;
}
__device__ __forceinline__ u64 add2(u64 a, u64 b) {
    u64 d;
    asm("add.rn.f32x2 %0,%1,%2;" : "=l"(d) : "l"(a), "l"(b));
    return d;
}
__device__ __forceinline__ u64 dup2(float x) {
    u64 r; unsigned u = __float_as_uint(x);
    asm("mov.b64 %0,{%1,%1};" : "=l"(r) : "r"(u));
    return r;
}
__device__ __forceinline__ u64 pack2(float a, float b) {
    u64 r; unsigned ua = __float_as_uint(a), ub = __float_as_uint(b);
    asm("mov.b64 %0,{%1,%2};" : "=l"(r) : "r"(ua), "r"(ub));
    return r;
}
__device__ __forceinline__ float2 unpk2(u64 v) {
    unsigned lo, hi;
    asm("mov.b64 {%0,%1},%2;" : "=r"(lo), "=r"(hi) : "l"(v));
    return make_float2(__uint_as_float(lo), __uint_as_float(hi));
}
__device__ __forceinline__ u64 ld64s(const float* p) { return *reinterpret_cast<const u64*>(p); }
__device__ __forceinline__ void st64(float* p, u64 v) { *reinterpret_cast<u64*>(p) = v; }

__device__ __forceinline__ float sigf(float x)  { return __fdividef(1.f, 1.f + __expf(-x)); }
__device__ __forceinline__ float tanhf_(float x){ return __fdividef(2.f, 1.f + __expf(-2.f * x)) - 1.f; }
// 3-MUFU gated activation: tanh(F)*sigmoid(G)
__device__ __forceinline__ float gated(float F, float G) {
    float e2f = __expf(2.f * F);
    float eg  = __expf(-G);
    return (e2f - 1.f) * __frcp_rn((e2f + 1.f) * (1.f + eg));
}

// ---------------- tcgen05 helpers ----------------
__device__ __forceinline__ uint32_t smem_u32(const void* p) {
    uint32_t a;
    asm("{ .reg .u64 t; cvta.to.shared.u64 t, %1; cvt.u32.u64 %0, t; }" : "=r"(a) : "l"(p));
    return a;
}
__device__ __forceinline__ uint32_t elect1() {
    uint32_t p;
    asm volatile("{\n\t.reg .pred p;\n\telect.sync _|p, 0xFFFFFFFF;\n\tselp.b32 %0,1,0,p;\n\t}" : "=r"(p));
    return p;
}
static constexpr uint64_t DESC_BASE_SW128 =
    (uint64_t(2) << 61) | (uint64_t(1) << 46) | (uint64_t(64) << 32) | (uint64_t(1) << 16);
#define MK_DESC(a) (DESC_BASE_SW128 | ((uint64_t)((a) >> 4) & 0x3FFF))

#if HAS_TC
__device__ __forceinline__ void mma_f16_ss(uint32_t d, uint64_t ad, uint64_t bd,
                                           uint32_t idesc, uint32_t en) {
    asm volatile(
        "{\n\t.reg .pred p;\n\tsetp.ne.u32 p,%5,0;\n\t"
        "tcgen05.mma.cta_group::1.kind::f16 [%0], %1, %2, %3, {%4,%4,%4,%4}, p;\n\t}"
        :: "r"(d), "l"(ad), "l"(bd), "r"(idesc), "r"(0u), "r"(en) : "memory");
}
__device__ __forceinline__ void mma_f16_ts(uint32_t d, uint32_t a, uint64_t bd,
                                           uint32_t idesc, uint32_t en) {
    asm volatile(
        "{\n\t.reg .pred p;\n\tsetp.ne.u32 p,%5,0;\n\t"
        "tcgen05.mma.cta_group::1.kind::f16 [%0], [%1], %2, %3, {%4,%4,%4,%4}, p;\n\t}"
        :: "r"(d), "r"(a), "l"(bd), "r"(idesc), "r"(0u), "r"(en) : "memory");
}

#define TC_ALLOC(sa, n)  asm volatile("tcgen05.alloc.cta_group::1.sync.aligned.shared::cta.b32 [%0], %1;" :: "r"(sa), "r"(n) : "memory")
#define TC_DEALLOC(t, n) asm volatile("tcgen05.dealloc.cta_group::1.sync.aligned.b32 %0, %1;" :: "r"(t), "r"(n))
#define TC_RELINQ()      asm volatile("tcgen05.relinquish_alloc_permit.cta_group::1.sync.aligned;")
#define TC_COMMIT(m)     asm volatile("tcgen05.commit.cta_group::1.mbarrier::arrive::one.shared::cluster.b64 [%0];" :: "r"(m) : "memory")
#define TC_FENCE_AFTER()  asm volatile("tcgen05.fence::after_thread_sync;" ::: "memory")
#define TC_FENCE_BEFORE() asm volatile("tcgen05.fence::before_thread_sync;" ::: "memory")
#define TC_WAIT_LD()     asm volatile("tcgen05.wait::ld.sync.aligned;" ::: "memory")
#define TC_WAIT_ST()     asm volatile("tcgen05.wait::st.sync.aligned;" ::: "memory")

#define LDTM_X32(r, ta)                                                    \
    asm volatile("tcgen05.ld.sync.aligned.32x32b.x32.b32 "                 \
        "{%0,%1,%2,%3,%4,%5,%6,%7,%8,%9,%10,%11,%12,%13,%14,%15,"          \
        "%16,%17,%18,%19,%20,%21,%22,%23,%24,%25,%26,%27,%28,%29,%30,%31}, [%32];" \
        : "=r"((r)[0]), "=r"((r)[1]), "=r"((r)[2]), "=r"((r)[3]),          \
          "=r"((r)[4]), "=r"((r)[5]), "=r"((r)[6]), "=r"((r)[7]),          \
          "=r"((r)[8]), "=r"((r)[9]), "=r"((r)[10]), "=r"((r)[11]),        \
          "=r"((r)[12]), "=r"((r)[13]), "=r"((r)[14]), "=r"((r)[15]),      \
          "=r"((r)[16]), "=r"((r)[17]), "=r"((r)[18]), "=r"((r)[19]),      \
          "=r"((r)[20]), "=r"((r)[21]), "=r"((r)[22]), "=r"((r)[23]),      \
          "=r"((r)[24]), "=r"((r)[25]), "=r"((r)[26]), "=r"((r)[27]),      \
          "=r"((r)[28]), "=r"((r)[29]), "=r"((r)[30]), "=r"((r)[31])       \
        : "r"(ta))

#define LDTM_X16(r, ta)                                                    \
    asm volatile("tcgen05.ld.sync.aligned.32x32b.x16.b32 "                 \
        "{%0,%1,%2,%3,%4,%5,%6,%7,%8,%9,%10,%11,%12,%13,%14,%15}, [%16];"  \
        : "=r"((r)[0]), "=r"((r)[1]), "=r"((r)[2]), "=r"((r)[3]),          \
          "=r"((r)[4]), "=r"((r)[5]), "=r"((r)[6]), "=r"((r)[7]),          \
          "=r"((r)[8]), "=r"((r)[9]), "=r"((r)[10]), "=r"((r)[11]),        \
          "=r"((r)[12]), "=r"((r)[13]), "=r"((r)[14]), "=r"((r)[15])       \
        : "r"(ta))

#define TC_ST8(ta, r)                                                      \
    asm volatile("tcgen05.st.sync.aligned.32x32b.x8.b32 [%0], "            \
        "{%1,%2,%3,%4,%5,%6,%7,%8};"                                       \
        :: "r"(ta),                                                        \
           "r"((r)[0]), "r"((r)[1]), "r"((r)[2]), "r"((r)[3]),             \
           "r"((r)[4]), "r"((r)[5]), "r"((r)[6]), "r"((r)[7])              \
        : "memory")
#endif  // HAS_TC

#define FENCE_ASYNC()    asm volatile("fence.proxy.async.shared::cta;" ::: "memory")
#define MBAR_INIT(m, c)  asm volatile("mbarrier.init.shared.b64 [%0], %1;" :: "r"(m), "r"(c) : "memory")

#define MBAR_WAIT(mb, ph) do {                                             \
    uint32_t _m = (mb), _p = (ph), _d;                                     \
    asm volatile("{\n\t.reg .pred p;\n\t"                                  \
        "mbarrier.try_wait.parity.acquire.cta.shared::cta.b64 p, [%1], %2;\n\t" \
        "selp.b32 %0,1,0,p;\n\t}" : "=r"(_d) : "r"(_m), "r"(_p) : "memory"); \
    if (!_d) {                                                             \
        asm volatile("{\n\t.reg .pred P1;\n\t"                             \
            "WL_%=:\n\t"                                                   \
            "mbarrier.try_wait.parity.acquire.cta.shared::cta.b64 P1, [%0], %1, 0x989680;\n\t" \
            "@P1 bra.uni WD_%=;\n\t"                                       \
            "bra.uni WL_%=;\n\t"                                           \
            "WD_%=:\n\t}" :: "r"(_m), "r"(_p) : "memory");                 \
    }                                                                      \
} while (0)

__device__ __forceinline__ unsigned bf2(__nv_bfloat16 a, __nv_bfloat16 b) {
    return (unsigned)__bfloat16_as_ushort(a) | ((unsigned)__bfloat16_as_ushort(b) << 16);
}
__device__ __forceinline__ unsigned hi_lo_pack(float x0, float x1, unsigned& lo_out) {
    __nv_bfloat16 h0 = __float2bfloat16_rn(x0);
    __nv_bfloat16 h1 = __float2bfloat16_rn(x1);
    lo_out = bf2(__float2bfloat16_rn(x0 - __bfloat162float(h0)),
                 __float2bfloat16_rn(x1 - __bfloat162float(h1)));
    return bf2(h0, h1);
}

// ---------------- kernel 0: weight prep (tc path) ----------------
__global__ void __launch_bounds__(512, 1)
wn_prep(const float* __restrict__ wf, const float* __restrict__ wg,
        const float* __restrict__ wr, const float* __restrict__ ws) {
    int L = blockIdx.x;
    int tid = threadIdx.x;
    unsigned char* d0 = g_wfgp + (size_t)L * 65536;
#pragma unroll
    for (int it = 0; it < 8; ++it) {
        int v = tid + 512 * it;               // 0..4095
        int c2 = v >> 5, cp = v & 31;
        const float* src = (c2 < 64) ? (wf + (size_t)L * 8192 + c2 * 128 + cp * 4)
                                     : (wg + (size_t)L * 8192 + (c2 - 64) * 128 + cp * 4);
        float4 wv = *(const float4*)src;      // {cin0 tap0, cin0 tap1, cin1 tap0, cin1 tap1}
        unsigned off = (unsigned)(c2 * 128 + cp * 4);
        unsigned sw = off ^ ((off >> 3) & 0x70);
        unsigned lo, hi;
        hi = hi_lo_pack(wv.x, wv.z, lo);      // tap0 (prev)
        *(unsigned*)(d0 + sw)         = hi;
        *(unsigned*)(d0 + 16384 + sw) = lo;
        hi = hi_lo_pack(wv.y, wv.w, lo);      // tap1 (cur)
        *(unsigned*)(d0 + 32768 + sw) = hi;
        *(unsigned*)(d0 + 49152 + sw) = lo;
    }
    unsigned char* d1 = g_wrp + (size_t)L * 16384;
#pragma unroll
    for (int it = 0; it < 4; ++it) {
        int v = tid + 512 * it;               // 0..2047
        int c = v >> 5, cp = v & 31;
        float2 wv = *(const float2*)(wr + (size_t)L * 4096 + c * 64 + cp * 2);
        unsigned off = (unsigned)(c * 128 + cp * 4);
        unsigned sw = off ^ ((off >> 3) & 0x70);
        unsigned lo, hi;
        hi = hi_lo_pack(wv.x, wv.y, lo);
        *(unsigned*)(d1 + sw)        = hi;
        *(unsigned*)(d1 + 8192 + sw) = lo;
    }
    unsigned char* d2 = g_wsp + (size_t)L * 65536;
#pragma unroll
    for (int it = 0; it < 8; ++it) {
        int v = tid + 512 * it;               // 0..4095
        int row = v >> 4, c4 = v & 15;
        float4 wv = *(const float4*)(ws + (size_t)L * (CS_ * CR_) + row * 64 + c4 * 4);
        int q = row >> 7, c = row & 127;
        unsigned lo0, hi0, lo1, hi1;
        hi0 = hi_lo_pack(wv.x, wv.y, lo0);
        hi1 = hi_lo_pack(wv.z, wv.w, lo1);
        unsigned off = (unsigned)(c * 128 + c4 * 8);
        unsigned sw = off ^ ((off >> 3) & 0x70);
        unsigned char* base = d2 + q * 32768;
        *(u64*)(base + sw)         = (u64)hi0 | ((u64)hi1 << 32);
        *(u64*)(base + 16384 + sw) = (u64)lo0 | ((u64)lo1 << 32);
    }
}

// ---------------- kernel 1: input 1x1 conv ([b][c][t]) ----------------
__global__ void wn_input(const float* __restrict__ x,
                         const float* __restrict__ w,
                         const float* __restrict__ bias) {
    __shared__ float sw[CR_ * CIN_];
    __shared__ float sb[CR_];
    int tid = threadIdx.x;
    for (int k = tid; k < CR_ * CIN_; k += 256) sw[k] = w[k];
    if (tid < CR_) sb[tid] = bias[tid];
    __syncthreads();
    int gt = blockIdx.x * 256 + tid;
    int b = gt >> 12;
    int t = gt & (T_ - 1);
    float xv[CIN_];
#pragma unroll
    for (int ci = 0; ci < CIN_; ++ci) xv[ci] = x[(b * CIN_ + ci) * T_ + t];
#pragma unroll 4
    for (int c = 0; c < CR_; ++c) {
        float a = sb[c];
#pragma unroll
        for (int ci = 0; ci < CIN_; ++ci) a = fmaf(sw[c * CIN_ + ci], xv[ci], a);
        g_h0[(b * CR_ + c) * T_ + t] = a;
    }
}

// ---------------- kernel 2a: scalar WaveNet layer (fallback) ----------------
#define SMEM_L ((16384 + 16384 + 16384 + 4096) * 4)

__global__ void __launch_bounds__(512, 1)
wn_layer(const float* __restrict__ wf, const float* __restrict__ bf,
         const float* __restrict__ wg, const float* __restrict__ bg,
         const float* __restrict__ wr, const float* __restrict__ br,
         int layer, int dil, int flip) {
    extern __shared__ float sm[];
    float* s_cur  = sm;
    float* s_prev = sm + 16384;
    float* s_wfg  = sm + 32768;
    float* s_wr   = sm + 49152;

    const float* hin  = flip ? g_h1 : g_h0;
    float*       hout = flip ? g_h0 : g_h1;

    int tid = threadIdx.x;
    int b   = blockIdx.x >> 4;
    int tt0 = (blockIdx.x & 15) * TT_;
    const float* hb = hin + (size_t)b * CR_ * T_;

    for (int idx = tid; idx < 8192; idx += 512) {
        int c = idx >> 7, r = idx & 127, cin = r >> 1, tap = r & 1;
        int o = cin * 256 + tap * 128 + c;
        s_wfg[o]      = wf[idx];
        s_wfg[o + 64] = wg[idx];
    }
    for (int idx = tid; idx < 4096; idx += 512)
        s_wr[(idx & 63) * 64 + (idx >> 6)] = wr[idx];

    for (int k = tid; k < 4096; k += 512) {
        int row = k >> 6, col = (k & 63) << 2;
        *(float4*)(s_cur + row * 256 + col) =
            *(const float4*)(hb + row * T_ + tt0 + col);
    }
    for (int k = tid; k < 16384; k += 512) {
        int row = k >> 8, j = k & 255;
        int tp = tt0 - dil + j;
        s_prev[row * 256 + j] = (tp >= 0) ? hb[row * T_ + tp] : 0.f;
    }
    __syncthreads();

    int w = tid >> 5, l = tid & 31;
    int cb = w * 4;
    int j0 = 2 * l;

    u64 accF[4][4], accG[4][4];
#pragma unroll
    for (int k = 0; k < 4; ++k) {
        u64 bF = dup2(__ldg(bf + cb + k));
        u64 bG = dup2(__ldg(bg + cb + k));
#pragma unroll
        for (int p = 0; p < 4; ++p) { accF[k][p] = bF; accG[k][p] = bG; }
    }

    const float* curp = s_cur  + j0;
    const float* prvp = s_prev + j0;

#pragma unroll 4
    for (int cin = 0; cin < 64; ++cin) {
        u64 hc[4], hp[4];
#pragma unroll
        for (int p = 0; p < 4; ++p) {
            hc[p] = ld64s(curp + cin * 256 + 64 * p);
            hp[p] = ld64s(prvp + cin * 256 + 64 * p);
        }
        const float* wp = s_wfg + cin * 256 + cb;
        float F0[4], G0[4], F1[4], G1[4];
        *(float4*)F0 = *(const float4*)(wp);
        *(float4*)G0 = *(const float4*)(wp + 64);
        *(float4*)F1 = *(const float4*)(wp + 128);
        *(float4*)G1 = *(const float4*)(wp + 192);
#pragma unroll
        for (int k = 0; k < 4; ++k) {
            u64 wf0 = dup2(F0[k]), wf1 = dup2(F1[k]);
            u64 wg0 = dup2(G0[k]), wg1 = dup2(G1[k]);
#pragma unroll
            for (int p = 0; p < 4; ++p) {
                accF[k][p] = fma2(wf0, hp[p], accF[k][p]);
                accF[k][p] = fma2(wf1, hc[p], accF[k][p]);
                accG[k][p] = fma2(wg0, hp[p], accG[k][p]);
                accG[k][p] = fma2(wg1, hc[p], accG[k][p]);
            }
        }
    }

    u64 zr[4][4];
    float* zb = g_z + (size_t)layer * HSZ + (size_t)b * CR_ * T_ + tt0;
#pragma unroll
    for (int k = 0; k < 4; ++k)
#pragma unroll
        for (int p = 0; p < 4; ++p) {
            float2 fv = unpk2(accF[k][p]);
            float2 gv = unpk2(accG[k][p]);
            float z0 = tanhf_(fv.x) * sigf(gv.x);
            float z1 = tanhf_(fv.y) * sigf(gv.y);
            u64 zz = pack2(z0, z1);
            zr[k][p] = zz;
            st64(zb + (cb + k) * T_ + j0 + 64 * p, zz);
        }

    __syncthreads();
#pragma unroll
    for (int k = 0; k < 4; ++k)
#pragma unroll
        for (int p = 0; p < 4; ++p)
            st64(s_prev + (cb + k) * 256 + j0 + 64 * p, zr[k][p]);
    __syncthreads();

    u64 accR[4][4];
#pragma unroll
    for (int k = 0; k < 4; ++k) {
        u64 bR = dup2(__ldg(br + cb + k));
#pragma unroll
        for (int p = 0; p < 4; ++p) accR[k][p] = bR;
    }
#pragma unroll 4
    for (int cin = 0; cin < 64; ++cin) {
        u64 zc[4];
#pragma unroll
        for (int p = 0; p < 4; ++p) zc[p] = ld64s(prvp + cin * 256 + 64 * p);
        float R[4];
        *(float4*)R = *(const float4*)(s_wr + cin * 64 + cb);
#pragma unroll
        for (int k = 0; k < 4; ++k) {
            u64 wk = dup2(R[k]);
#pragma unroll
            for (int p = 0; p < 4; ++p) accR[k][p] = fma2(wk, zc[p], accR[k][p]);
        }
    }
    float* ho = hout + (size_t)b * CR_ * T_ + tt0;
#pragma unroll
    for (int k = 0; k < 4; ++k)
#pragma unroll
        for (int p = 0; p < 4; ++p) {
            u64 hv = ld64s(s_cur + (cb + k) * 256 + j0 + 64 * p);
            st64(ho + (cb + k) * T_ + j0 + 64 * p, add2(accR[k][p], hv));
        }
}

// ---------------- kernel 2b: persistent tcgen05 layer (4 tiles/CTA, 2 CTAs/SM) ----------------
// TMEM per tile: A prev-hi 0..31 | cur-hi 32..63 | prev-lo 64..95 | cur-lo 96..127; D1 128..255
// after MMA1: z-hi 0..31 | z-lo 32..63 | D2 64..127
// smem: [256..1024) biases | Wfg 64KB | Wr 16KB | z-image scratch 16KB (hi then lo)
#define SB_BIAS 256
#define WP3_H 1024
#define WP3_L 17408
#define WC3_H 33792
#define WC3_L 50176
#define WR3_H 66560
#define WR3_L 74752
#define ZIMG  82944
#define SMEM_LT3 99328

#define ID1 0x8200490u   // f32 acc | bf16 | N=128 | M=128
#define ID2 0x8100490u   // f32 acc | bf16 | N=64  | M=128

__global__ void __launch_bounds__(512, 2)
wn_layer_tc(const float* __restrict__ bf, const float* __restrict__ bg,
            const float* __restrict__ br,
            int layer, int dil, int flip) {
#if HAS_TC
    extern __shared__ char smc[];
    uint32_t sb = smem_u32(smc);
    int tid = threadIdx.x, wid = tid >> 5, lane = tid & 31;
    int sub = wid & 3;                // TMEM subpartition
    int cg  = wid >> 2;               // cin/col group (0..3)
    int gt0 = blockIdx.x * NTPC;      // first tile (4 consecutive, same b)
    int b   = gt0 >> 5;
    int tl  = sub * 32 + lane;        // local t (0..127)
    const float* hin = flip ? g_h1 : g_h0;
    float* hout = flip ? g_h0 : g_h1;
    const float* hb = hin + (size_t)b * CR_ * T_;
    float* hob = hout + (size_t)b * CR_ * T_;

    if (wid == 0) TC_ALLOC(sb, 256);
    if (tid == 0) { MBAR_INIT(sb + 8, 1); MBAR_INIT(sb + 16, 1); }
    __syncthreads();
    uint32_t tmem;
    asm volatile("ld.shared.b32 %0, [%1];" : "=r"(tmem) : "r"(sb));
    if (wid == 0) TC_RELINQ();

    // ---- stage biases + weights ONCE (amortized over 4 tiles) ----
    {
        float* sbias = (float*)(smc + SB_BIAS);
        if (tid < 64)        sbias[tid] = __ldg(bf + tid);
        else if (tid < 128)  sbias[tid] = __ldg(bg + tid - 64);
        else if (tid < 192)  sbias[tid] = __ldg(br + tid - 128);

        const uint4* wsrc = (const uint4*)(g_wfgp + (size_t)layer * 65536);
        uint4* wdst = (uint4*)(smc + WP3_H);
#pragma unroll
        for (int it = 0; it < 8; ++it) {
            int idx = tid + 512 * it;          // 0..4095
            wdst[idx] = wsrc[idx];
        }
        const uint4* rsrc = (const uint4*)(g_wrp + (size_t)layer * 16384);
        uint4* rdst = (uint4*)(smc + WR3_H);
#pragma unroll
        for (int it = 0; it < 2; ++it) {
            int idx = tid + 512 * it;          // 0..1023
            rdst[idx] = rsrc[idx];
        }
    }

    int p1 = 0, p2 = 0;
    for (int j = 0; j < NTPC; ++j) {
        int gt  = gt0 + j;
        int tt0 = (gt & 31) * TTL;
        int tg  = tt0 + tl;

        // ---- stage A (h) -> TMEM ----
        {
            unsigned cur_h[8], cur_l[8], prv_h[8], prv_l[8];
            bool pv = (tg - dil) >= 0;
#pragma unroll
            for (int k = 0; k < 8; ++k) {
                int cin = 16 * cg + 2 * k;
                const float* p0 = hb + (size_t)cin * T_;
                const float* p1p = p0 + T_;
                cur_h[k] = hi_lo_pack(p0[tg], p1p[tg], cur_l[k]);
                float a0 = 0.f, a1 = 0.f;
                if (pv) { a0 = p0[tg - dil]; a1 = p1p[tg - dil]; }
                prv_h[k] = hi_lo_pack(a0, a1, prv_l[k]);
            }
            uint32_t wo = ((uint32_t)sub << 21) + (uint32_t)(cg * 8);
            TC_ST8(tmem + 0  + wo, prv_h);
            TC_ST8(tmem + 32 + wo, cur_h);
            TC_ST8(tmem + 64 + wo, prv_l);
            TC_ST8(tmem + 96 + wo, cur_l);
            TC_WAIT_ST();
        }
        TC_FENCE_BEFORE();
        FENCE_ASYNC();
        __syncthreads();

        // ---- MMA1 (TS): 24 dispatches ----
        if (wid == 0 && elect1()) {
            TC_FENCE_AFTER();
            uint64_t wph = MK_DESC(sb + WP3_H), wpl = MK_DESC(sb + WP3_L);
            uint64_t wch = MK_DESC(sb + WC3_H), wcl = MK_DESC(sb + WC3_L);
#pragma unroll
            for (int k = 0; k < 4; ++k)
                mma_f16_ts(tmem + 128, tmem + 0  + k * 8, wph + 2 * k, ID1, k > 0 ? 1u : 0u);
#pragma unroll
            for (int k = 0; k < 4; ++k)
                mma_f16_ts(tmem + 128, tmem + 32 + k * 8, wch + 2 * k, ID1, 1u);
#pragma unroll
            for (int k = 0; k < 4; ++k)
                mma_f16_ts(tmem + 128, tmem + 0  + k * 8, wpl + 2 * k, ID1, 1u);
#pragma unroll
            for (int k = 0; k < 4; ++k)
                mma_f16_ts(tmem + 128, tmem + 32 + k * 8, wcl + 2 * k, ID1, 1u);
#pragma unroll
            for (int k = 0; k < 4; ++k)
                mma_f16_ts(tmem + 128, tmem + 64 + k * 8, wph + 2 * k, ID1, 1u);
#pragma unroll
            for (int k = 0; k < 4; ++k)
                mma_f16_ts(tmem + 128, tmem + 96 + k * 8, wch + 2 * k, ID1, 1u);
            TC_COMMIT(sb + 8);
        }
        MBAR_WAIT(sb + 8, p1);
        p1 ^= 1;
        TC_FENCE_AFTER();

        // ---- z epilogue: z -> TMEM + hi-image into scratch ----
        unsigned zl[8];
        {
            const float* sbias = (const float*)(smc + SB_BIAS);
            uint32_t fr[16], gr[16];
            LDTM_X16(fr, tmem + 128 + 16 * cg);
            LDTM_X16(gr, tmem + 192 + 16 * cg);
            TC_WAIT_LD();
            unsigned zh[8];
#pragma unroll
            for (int jj = 0; jj < 8; ++jj) {
                int c0 = 16 * cg + 2 * jj;
                float F0 = __uint_as_float(fr[2 * jj])     + sbias[c0];
                float G0 = __uint_as_float(gr[2 * jj])     + sbias[64 + c0];
                float F1 = __uint_as_float(fr[2 * jj + 1]) + sbias[c0 + 1];
                float G1 = __uint_as_float(gr[2 * jj + 1]) + sbias[64 + c0 + 1];
                zh[jj] = hi_lo_pack(gated(F0, G0), gated(F1, G1), zl[jj]);
            }
            uint32_t wo = ((uint32_t)sub << 21) + (uint32_t)(cg * 8);
            TC_ST8(tmem + 0  + wo, zh);
            TC_ST8(tmem + 32 + wo, zl);
            TC_WAIT_ST();
            // hi image rows into scratch (conflict-free via swizzle)
            unsigned tx = (unsigned)((tl & 7) * 16);
            unsigned b0 = (unsigned)(cg * 32);
            char* ip = smc + ZIMG + tl * 128;
            *(uint4*)(ip + (b0 ^ tx))        = make_uint4(zh[0], zh[1], zh[2], zh[3]);
            *(uint4*)(ip + ((b0 + 16) ^ tx)) = make_uint4(zh[4], zh[5], zh[6], zh[7]);
        }
        TC_FENCE_BEFORE();
        __syncthreads();

        // ---- MMA2 (TS): 12 dispatches ----
        if (wid == 0 && elect1()) {
            TC_FENCE_AFTER();
            uint64_t rh = MK_DESC(sb + WR3_H), rl = MK_DESC(sb + WR3_L);
#pragma unroll
            for (int k = 0; k < 4; ++k)
                mma_f16_ts(tmem + 64, tmem + 0  + k * 8, rh + 2 * k, ID2, k > 0 ? 1u : 0u);
#pragma unroll
            for (int k = 0; k < 4; ++k)
                mma_f16_ts(tmem + 64, tmem + 0  + k * 8, rl + 2 * k, ID2, 1u);
#pragma unroll
            for (int k = 0; k < 4; ++k)
                mma_f16_ts(tmem + 64, tmem + 32 + k * 8, rh + 2 * k, ID2, 1u);
            TC_COMMIT(sb + 16);
        }

        // ---- prefetch residual h (overlap with MMA2) ----
        float hc[16];
#pragma unroll
        for (int k = 0; k < 16; ++k)
            hc[k] = hb[(size_t)(16 * cg + k) * T_ + tg];

        // ---- copy hi image -> g_zsw (overlap with MMA2) ----
        unsigned char* img = g_zsw + ((size_t)layer * 512 + (gt >> 1)) * 65536;
        {
            const uint4* sh = (const uint4*)(smc + ZIMG);
            uint4* dh = (uint4*)img + ((gt & 1) << 10);
#pragma unroll
            for (int j2 = 0; j2 < 2; ++j2)
                dh[tid + 512 * j2] = sh[tid + 512 * j2];
        }
        __syncthreads();   // scratch fully copied out

        // ---- lo image into scratch, then copy out ----
        {
            unsigned tx = (unsigned)((tl & 7) * 16);
            unsigned b0 = (unsigned)(cg * 32);
            char* ip = smc + ZIMG + tl * 128;
            *(uint4*)(ip + (b0 ^ tx))        = make_uint4(zl[0], zl[1], zl[2], zl[3]);
            *(uint4*)(ip + ((b0 + 16) ^ tx)) = make_uint4(zl[4], zl[5], zl[6], zl[7]);
        }
        __syncthreads();
        {
            const uint4* sl = (const uint4*)(smc + ZIMG);
            uint4* dl = (uint4*)(img + 32768) + ((gt & 1) << 10);
#pragma unroll
            for (int j2 = 0; j2 < 2; ++j2)
                dl[tid + 512 * j2] = sl[tid + 512 * j2];
        }

        MBAR_WAIT(sb + 16, p2);
        p2 ^= 1;
        TC_FENCE_AFTER();

        // ---- residual epilogue ----
        {
            const float* sbias = (const float*)(smc + SB_BIAS);
            uint32_t rr[16];
            LDTM_X16(rr, tmem + 64 + 16 * cg);
            TC_WAIT_LD();
#pragma unroll
            for (int k = 0; k < 16; ++k) {
                int c = 16 * cg + k;
                hob[(size_t)c * T_ + tg] =
                    __uint_as_float(rr[k]) + sbias[128 + c] + hc[k];
            }
        }
        __syncthreads();   // TMEM/scratch safe for next tile
    }
    if (wid == 0) TC_DEALLOC(tmem, 256);
#else
    volatile __shared__ int s_marker[8];
    s_marker[threadIdx.x & 7] = (int)threadIdx.x;
    if (s_marker[0] == -12345) g_h0[0] = bf[0] + bg[0] + br[0];
#endif
}

// ---------------- kernel 3a: scalar skip reduction (fallback) ----------------
#define SMEM_S ((16384 + 8192) * 4)

__global__ void __launch_bounds__(512, 1)
wn_skip(const float* __restrict__ ws, const float* __restrict__ bs,
        float* __restrict__ out) {
    extern __shared__ float sm[];
    float* s_z = sm;
    float* s_w = sm + 16384;

    int tid = threadIdx.x;
    int b   = blockIdx.x >> 4;
    int tt0 = (blockIdx.x & 15) * TT_;
    int w = tid >> 5, l = tid & 31;
    int j0 = 2 * l;

    for (int q = 0; q < 2; ++q) {
        int cq = q * 128 + w * 8;
        u64 acc[8][4];
#pragma unroll
        for (int k = 0; k < 8; ++k) {
            float s = 0.f;
            for (int i = 0; i < L_; ++i) s += __ldg(bs + i * CS_ + cq + k);
            u64 d = dup2(s);
#pragma unroll
            for (int p = 0; p < 4; ++p) acc[k][p] = d;
        }
        for (int i = 0; i < L_; ++i) {
            __syncthreads();
            const float* zsrc = g_z + (size_t)i * HSZ + (size_t)b * CR_ * T_ + tt0;
            for (int k = tid; k < 4096; k += 512) {
                int row = k >> 6, col = (k & 63) << 2;
                *(float4*)(s_z + row * 256 + col) =
                    *(const float4*)(zsrc + row * T_ + col);
            }
            const float* wsrc = ws + i * (CS_ * CR_) + q * 128 * 64;
            for (int k2 = tid; k2 < 8192; k2 += 512) {
                int c = k2 >> 6, cin = k2 & 63;
                s_w[cin * 128 + c] = wsrc[k2];
            }
            __syncthreads();
            const float* zp = s_z + j0;
#pragma unroll 4
            for (int cin = 0; cin < 64; ++cin) {
                u64 zc[4];
#pragma unroll
                for (int p = 0; p < 4; ++p) zc[p] = ld64s(zp + cin * 256 + 64 * p);
                float Wv[8];
                *(float4*)(Wv)     = *(const float4*)(s_w + cin * 128 + w * 8);
                *(float4*)(Wv + 4) = *(const float4*)(s_w + cin * 128 + w * 8 + 4);
#pragma unroll
                for (int k = 0; k < 8; ++k) {
                    u64 wk = dup2(Wv[k]);
#pragma unroll
                    for (int p = 0; p < 4; ++p) acc[k][p] = fma2(wk, zc[p], acc[k][p]);
                }
            }
        }
        float* ob = out + (size_t)b * CS_ * T_ + tt0;
#pragma unroll
        for (int k = 0; k < 8; ++k)
#pragma unroll
            for (int p = 0; p < 4; ++p)
                st64(ob + (cq + k) * T_ + j0 + 64 * p, acc[k][p]);
    }
}

// ---------------- kernel 3b: tcgen05 skip reduction (pure-copy dbuf) ----------------
#define SK_B0H 1024
#define SK_B0L 33792
#define SK_B1H 66560
#define SK_B1L 99328
#define SK_A   132096          // Ah0 | Al0 | Ah1 | Al1 (16 KB each)
#define SK_SMEM (SK_A + 65536 + 64)

#define SK_IDESC 0x8400490u   // f32 acc | bf16 a,b | N=256 | M=128

__global__ void __launch_bounds__(512, 1)
wn_skip_tc(const float* __restrict__ bs, float* __restrict__ out) {
#if HAS_TC
    extern __shared__ char smc[];
    uint32_t sb = smem_u32(smc);

    int tid  = threadIdx.x;
    int wid  = tid >> 5;
    int lane = tid & 31;
    int b    = blockIdx.x >> 4;
    int tt0  = (blockIdx.x & 15) * TT_;

    if (wid == 0) TC_ALLOC(sb, 512);
    if (tid == 0) MBAR_INIT(sb + 8, 1);
    __syncthreads();
    uint32_t tmem;
    asm volatile("ld.shared.b32 %0, [%1];" : "=r"(tmem) : "r"(sb));
    if (wid == 0) TC_RELINQ();

    // prologue: copy z(0) tile image into buffer 0 (pure uint4 copies)
    {
        const uint4* src = (const uint4*)(g_zsw + ((size_t)0 * 512 + blockIdx.x) * 65536);
#pragma unroll
        for (int k2 = tid; k2 < 2048; k2 += 512) {
            ((uint4*)(smc + SK_B0H))[k2] = src[k2];
            ((uint4*)(smc + SK_B0L))[k2] = src[k2 + 2048];
        }
    }

    int ph = 0;
    for (int i = 0; i < L_; ++i) {
        int buf = i & 1;
        if (i > 0) { MBAR_WAIT(sb + 8, ph); ph ^= 1; }   // MMA(i-1) done

        // ---- stage A: pure copy of pre-converted ws images ----
        {
            const uint4* asrc = (const uint4*)(g_wsp + (size_t)i * 65536);
            uint4* adst = (uint4*)(smc + SK_A);
#pragma unroll
            for (int it = 0; it < 8; ++it) {
                int idx = tid + 512 * it;      // 0..4095
                adst[idx] = asrc[idx];
            }
        }

        FENCE_ASYNC();
        __syncthreads();

        if (wid == 0 && elect1()) {
            uint64_t bdh = MK_DESC(sb + (buf ? SK_B1H : SK_B0H));
            uint64_t bdl = MK_DESC(sb + (buf ? SK_B1L : SK_B0L));
#pragma unroll
            for (int q = 0; q < 2; ++q) {
                uint64_t adh = MK_DESC(sb + SK_A + q * 32768);
                uint64_t adl = MK_DESC(sb + SK_A + q * 32768 + 16384);
                uint32_t dt  = tmem + q * 256;
#pragma unroll
                for (int k = 0; k < 4; ++k)
                    mma_f16_ss(dt, adh + 2 * k, bdh + 2 * k, SK_IDESC,
                               (i == 0 && k == 0) ? 0u : 1u);
#pragma unroll
                for (int k = 0; k < 4; ++k)
                    mma_f16_ss(dt, adh + 2 * k, bdl + 2 * k, SK_IDESC, 1u);
#pragma unroll
                for (int k = 0; k < 4; ++k)
                    mma_f16_ss(dt, adl + 2 * k, bdh + 2 * k, SK_IDESC, 1u);
            }
            TC_COMMIT(sb + 8);
        }

        // prefetch z(i+1) into the other buffer while MMA(i) runs
        if (i + 1 < L_) {
            int nb = buf ^ 1;
            const uint4* src = (const uint4*)(g_zsw + ((size_t)(i + 1) * 512 + blockIdx.x) * 65536);
            char* dsth = smc + (nb ? SK_B1H : SK_B0H);
            char* dstl = smc + (nb ? SK_B1L : SK_B0L);
#pragma unroll
            for (int k2 = tid; k2 < 2048; k2 += 512) {
                ((uint4*)dsth)[k2] = src[k2];
                ((uint4*)dstl)[k2] = src[k2 + 2048];
            }
        }
    }

    MBAR_WAIT(sb + 8, ph);
    TC_FENCE_AFTER();

    // epilogue: 16 warps; sub = lane-group, cq = 64-col chunk
    int sub = wid & 3;
    int cq  = wid >> 2;          // 0..3
#pragma unroll
    for (int q = 0; q < 2; ++q) {
        int c = q * 128 + sub * 32 + lane;
        float bsum = 0.f;
#pragma unroll
        for (int i = 0; i < L_; ++i) bsum += __ldg(bs + i * CS_ + c);
        float* op = out + (size_t)b * CS_ * T_ + (size_t)c * T_ + tt0 + cq * 64;
#pragma unroll
        for (int uu = 0; uu < 2; ++uu) {
            uint32_t dr[32];
            LDTM_X32(dr, tmem + q * 256 + cq * 64 + uu * 32);
            TC_WAIT_LD();
            float4 o4;
#pragma unroll
            for (int jj = 0; jj < 8; ++jj) {
                o4.x = __uint_as_float(dr[4 * jj + 0]) + bsum;
                o4.y = __uint_as_float(dr[4 * jj + 1]) + bsum;
                o4.z = __uint_as_float(dr[4 * jj + 2]) + bsum;
                o4.w = __uint_as_float(dr[4 * jj + 3]) + bsum;
                *(float4*)(op + uu * 32 + 4 * jj) = o4;
            }
        }
    }

    __syncthreads();
    if (wid == 0) TC_DEALLOC(tmem, 512);
#else
    volatile __shared__ int s_marker[8];
    s_marker[threadIdx.x & 7] = (int)threadIdx.x;
    if (s_marker[0] == -12345) out[0] = bs[0];
#endif
}

// ---------------- launch ----------------
extern "C" void kernel_launch(void* const* d_in, const int* in_sizes, int n_in,
                              void* d_out, int out_size) {
    const float* x    = (const float*)d_in[0];
    const float* w_in = (const float*)d_in[1];
    const float* b_in = (const float*)d_in[2];
    const float* w_f  = (const float*)d_in[3];
    const float* b_f  = (const float*)d_in[4];
    const float* w_g  = (const float*)d_in[5];
    const float* b_g  = (const float*)d_in[6];
    const float* w_s  = (const float*)d_in[7];
    const float* b_s  = (const float*)d_in[8];
    const float* w_r  = (const float*)d_in[9];
    const float* b_r  = (const float*)d_in[10];

    cudaFuncSetAttribute(wn_layer,    cudaFuncAttributeMaxDynamicSharedMemorySize, SMEM_L);
    cudaFuncSetAttribute(wn_layer_tc, cudaFuncAttributeMaxDynamicSharedMemorySize, SMEM_LT3);
    cudaFuncSetAttribute(wn_skip,     cudaFuncAttributeMaxDynamicSharedMemorySize, SMEM_S);
    cudaFuncSetAttribute(wn_skip_tc,  cudaFuncAttributeMaxDynamicSharedMemorySize, SK_SMEM);

    cudaFuncAttributes fa;
    bool use_tc = false;
    if (cudaFuncGetAttributes(&fa, wn_skip_tc) == cudaSuccess)
        use_tc = (fa.sharedSizeBytes == 0);
    if (use_tc) {
        if (cudaFuncGetAttributes(&fa, wn_layer_tc) != cudaSuccess ||
            fa.sharedSizeBytes != 0)
            use_tc = false;
    }

    if (use_tc)
        wn_prep<<<L_, 512>>>(w_f, w_g, w_r, w_s);

    wn_input<<<(B_ * T_) / 256, 256>>>(x, w_in, b_in);

    for (int i = 0; i < L_; ++i) {
        int d = 1 << (i % 10);
        if (use_tc)
            wn_layer_tc<<<B_ * (T_ / TTL) / NTPC, 512, SMEM_LT3>>>(
                b_f + i * CR_, b_g + i * CR_, b_r + i * CR_, i, d, i & 1);
        else
            wn_layer<<<B_ * (T_ / TT_), 512, SMEM_L>>>(
                w_f + (size_t)i * CR_ * CR_ * 2, b_f + i * CR_,
                w_g + (size_t)i * CR_ * CR_ * 2, b_g + i * CR_,
                w_r + (size_t)i * CR_ * CR_,     b_r + i * CR_,
                i, d, i & 1);
    }

    if (use_tc)
        wn_skip_tc<<<B_ * (T_ / TT_), 512, SK_SMEM>>>(b_s, (float*)d_out);
    else
        wn_skip<<<B_ * (T_ / TT_), 512, SMEM_S>>>(w_s, b_s, (float*)d_out);
}

// round 15
// speedup vs baseline: 1.0174x; 1.0174x over previous
#include <cuda_runtime.h>
#include <cuda_bf16.h>
#include <cstdint>

// ---------------- constants ----------------
#define B_   32
#define T_   4096
#define CIN_ 8
#define CR_  64
#define CS_  256
#define L_   20
#define TT_  256               // skip-kernel tile
#define TTL  128               // layer-kernel tile
#define NTPC 4                 // tiles per persistent layer CTA
#define HSZ  (B_ * CR_ * T_)

#if defined(__CUDA_ARCH_FEAT_SM103_ALL) || defined(__CUDA_ARCH_FEAT_SM100_ALL) || defined(__CUDA_ARCH_SPECIFIC__)
#define HAS_TC 1
#else
#define HAS_TC 0
#endif

typedef unsigned long long u64;

__device__ float g_h0[HSZ];
__device__ float g_h1[HSZ];
// fallback (scalar) path: fp32 z
__device__ float g_z[(size_t)L_ * HSZ];
// tc path: z as SW128 [t(256)][cin] bf16 tile images: [layer][skiptile(512)][hi 32KB | lo 32KB]
__device__ unsigned char g_zsw[(size_t)L_ * 512 * 65536];
// pre-converted weights (tile images, SW128, bf16 hi/lo)
__device__ unsigned char g_wfgp[(size_t)L_ * 65536];  // WP_H|WP_L|WC_H|WC_L (16KB each)
__device__ unsigned char g_wrp [(size_t)L_ * 16384];  // WR_H|WR_L (8KB each)
__device__ unsigned char g_wsp [(size_t)L_ * 65536];  // Ah0|Al0|Ah1|Al1 (16KB each)

// ---------------- f32x2 helpers (scalar fallback) ----------------
__device__ __forceinline__ u64 fma2(u64 a, u64 b, u64 c) {
    u64 d;
    asm("fma.rn.f32x2 %0,%1,%2,%3;" : "=l"(d) : "l"(a), "l"(b), "l"(c));
    return d;
}
__device__ __forceinline__ u64 add2(u64 a, u64 b) {
    u64 d;
    asm("add.rn.f32x2 %0,%1,%2;" : "=l"(d) : "l"(a), "l"(b));
    return d;
}
__device__ __forceinline__ u64 dup2(float x) {
    u64 r; unsigned u = __float_as_uint(x);
    asm("mov.b64 %0,{%1,%1};" : "=l"(r) : "r"(u));
    return r;
}
__device__ __forceinline__ u64 pack2(float a, float b) {
    u64 r; unsigned ua = __float_as_uint(a), ub = __float_as_uint(b);
    asm("mov.b64 %0,{%1,%2};" : "=l"(r) : "r"(ua), "r"(ub));
    return r;
}
__device__ __forceinline__ float2 unpk2(u64 v) {
    unsigned lo, hi;
    asm("mov.b64 {%0,%1},%2;" : "=r"(lo), "=r"(hi) : "l"(v));
    return make_float2(__uint_as_float(lo), __uint_as_float(hi));
}
__device__ __forceinline__ u64 ld64s(const float* p) { return *reinterpret_cast<const u64*>(p); }
__device__ __forceinline__ void st64(float* p, u64 v) { *reinterpret_cast<u64*>(p) = v; }

__device__ __forceinline__ float sigf(float x)  { return __fdividef(1.f, 1.f + __expf(-x)); }
__device__ __forceinline__ float tanhf_(float x){ return __fdividef(2.f, 1.f + __expf(-2.f * x)) - 1.f; }
// 3-MUFU gated activation: tanh(F)*sigmoid(G)
__device__ __forceinline__ float gated(float F, float G) {
    float e2f = __expf(2.f * F);
    float eg  = __expf(-G);
    return (e2f - 1.f) * __frcp_rn((e2f + 1.f) * (1.f + eg));
}

// ---------------- tcgen05 helpers ----------------
__device__ __forceinline__ uint32_t smem_u32(const void* p) {
    uint32_t a;
    asm("{ .reg .u64 t; cvta.to.shared.u64 t, %1; cvt.u32.u64 %0, t; }" : "=r"(a) : "l"(p));
    return a;
}
__device__ __forceinline__ uint32_t elect1() {
    uint32_t p;
    asm volatile("{\n\t.reg .pred p;\n\telect.sync _|p, 0xFFFFFFFF;\n\tselp.b32 %0,1,0,p;\n\t}" : "=r"(p));
    return p;
}
static constexpr uint64_t DESC_BASE_SW128 =
    (uint64_t(2) << 61) | (uint64_t(1) << 46) | (uint64_t(64) << 32) | (uint64_t(1) << 16);
#define MK_DESC(a) (DESC_BASE_SW128 | ((uint64_t)((a) >> 4) & 0x3FFF))

#if HAS_TC
__device__ __forceinline__ void mma_f16_ss(uint32_t d, uint64_t ad, uint64_t bd,
                                           uint32_t idesc, uint32_t en) {
    asm volatile(
        "{\n\t.reg .pred p;\n\tsetp.ne.u32 p,%5,0;\n\t"
        "tcgen05.mma.cta_group::1.kind::f16 [%0], %1, %2, %3, {%4,%4,%4,%4}, p;\n\t}"
        :: "r"(d), "l"(ad), "l"(bd), "r"(idesc), "r"(0u), "r"(en) : "memory");
}
__device__ __forceinline__ void mma_f16_ts(uint32_t d, uint32_t a, uint64_t bd,
                                           uint32_t idesc, uint32_t en) {
    asm volatile(
        "{\n\t.reg .pred p;\n\tsetp.ne.u32 p,%5,0;\n\t"
        "tcgen05.mma.cta_group::1.kind::f16 [%0], [%1], %2, %3, {%4,%4,%4,%4}, p;\n\t}"
        :: "r"(d), "r"(a), "l"(bd), "r"(idesc), "r"(0u), "r"(en) : "memory");
}

#define TC_ALLOC(sa, n)  asm volatile("tcgen05.alloc.cta_group::1.sync.aligned.shared::cta.b32 [%0], %1;" :: "r"(sa), "r"(n) : "memory")
#define TC_DEALLOC(t, n) asm volatile("tcgen05.dealloc.cta_group::1.sync.aligned.b32 %0, %1;" :: "r"(t), "r"(n))
#define TC_RELINQ()      asm volatile("tcgen05.relinquish_alloc_permit.cta_group::1.sync.aligned;")
#define TC_COMMIT(m)     asm volatile("tcgen05.commit.cta_group::1.mbarrier::arrive::one.shared::cluster.b64 [%0];" :: "r"(m) : "memory")
#define TC_FENCE_AFTER()  asm volatile("tcgen05.fence::after_thread_sync;" ::: "memory")
#define TC_FENCE_BEFORE() asm volatile("tcgen05.fence::before_thread_sync;" ::: "memory")
#define TC_WAIT_LD()     asm volatile("tcgen05.wait::ld.sync.aligned;" ::: "memory")
#define TC_WAIT_ST()     asm volatile("tcgen05.wait::st.sync.aligned;" ::: "memory")

#define LDTM_X32(r, ta)                                                    \
    asm volatile("tcgen05.ld.sync.aligned.32x32b.x32.b32 "                 \
        "{%0,%1,%2,%3,%4,%5,%6,%7,%8,%9,%10,%11,%12,%13,%14,%15,"          \
        "%16,%17,%18,%19,%20,%21,%22,%23,%24,%25,%26,%27,%28,%29,%30,%31}, [%32];" \
        : "=r"((r)[0]), "=r"((r)[1]), "=r"((r)[2]), "=r"((r)[3]),          \
          "=r"((r)[4]), "=r"((r)[5]), "=r"((r)[6]), "=r"((r)[7]),          \
          "=r"((r)[8]), "=r"((r)[9]), "=r"((r)[10]), "=r"((r)[11]),        \
          "=r"((r)[12]), "=r"((r)[13]), "=r"((r)[14]), "=r"((r)[15]),      \
          "=r"((r)[16]), "=r"((r)[17]), "=r"((r)[18]), "=r"((r)[19]),      \
          "=r"((r)[20]), "=r"((r)[21]), "=r"((r)[22]), "=r"((r)[23]),      \
          "=r"((r)[24]), "=r"((r)[25]), "=r"((r)[26]), "=r"((r)[27]),      \
          "=r"((r)[28]), "=r"((r)[29]), "=r"((r)[30]), "=r"((r)[31])       \
        : "r"(ta))

#define LDTM_X16(r, ta)                                                    \
    asm volatile("tcgen05.ld.sync.aligned.32x32b.x16.b32 "                 \
        "{%0,%1,%2,%3,%4,%5,%6,%7,%8,%9,%10,%11,%12,%13,%14,%15}, [%16];"  \
        : "=r"((r)[0]), "=r"((r)[1]), "=r"((r)[2]), "=r"((r)[3]),          \
          "=r"((r)[4]), "=r"((r)[5]), "=r"((r)[6]), "=r"((r)[7]),          \
          "=r"((r)[8]), "=r"((r)[9]), "=r"((r)[10]), "=r"((r)[11]),        \
          "=r"((r)[12]), "=r"((r)[13]), "=r"((r)[14]), "=r"((r)[15])       \
        : "r"(ta))

#define TC_ST8(ta, r)                                                      \
    asm volatile("tcgen05.st.sync.aligned.32x32b.x8.b32 [%0], "            \
        "{%1,%2,%3,%4,%5,%6,%7,%8};"                                       \
        :: "r"(ta),                                                        \
           "r"((r)[0]), "r"((r)[1]), "r"((r)[2]), "r"((r)[3]),             \
           "r"((r)[4]), "r"((r)[5]), "r"((r)[6]), "r"((r)[7])              \
        : "memory")
#endif  // HAS_TC

#define FENCE_ASYNC()    asm volatile("fence.proxy.async.shared::cta;" ::: "memory")
#define MBAR_INIT(m, c)  asm volatile("mbarrier.init.shared.b64 [%0], %1;" :: "r"(m), "r"(c) : "memory")

#define MBAR_WAIT(mb, ph) do {                                             \
    uint32_t _m = (mb), _p = (ph), _d;                                     \
    asm volatile("{\n\t.reg .pred p;\n\t"                                  \
        "mbarrier.try_wait.parity.acquire.cta.shared::cta.b64 p, [%1], %2;\n\t" \
        "selp.b32 %0,1,0,p;\n\t}" : "=r"(_d) : "r"(_m), "r"(_p) : "memory"); \
    if (!_d) {                                                             \
        asm volatile("{\n\t.reg .pred P1;\n\t"                             \
            "WL_%=:\n\t"                                                   \
            "mbarrier.try_wait.parity.acquire.cta.shared::cta.b64 P1, [%0], %1, 0x989680;\n\t" \
            "@P1 bra.uni WD_%=;\n\t"                                       \
            "bra.uni WL_%=;\n\t"                                           \
            "WD_%=:\n\t}" :: "r"(_m), "r"(_p) : "memory");                 \
    }                                                                      \
} while (0)

__device__ __forceinline__ unsigned bf2(__nv_bfloat16 a, __nv_bfloat16 b) {
    return (unsigned)__bfloat16_as_ushort(a) | ((unsigned)__bfloat16_as_ushort(b) << 16);
}
__device__ __forceinline__ unsigned hi_lo_pack(float x0, float x1, unsigned& lo_out) {
    __nv_bfloat16 h0 = __float2bfloat16_rn(x0);
    __nv_bfloat16 h1 = __float2bfloat16_rn(x1);
    lo_out = bf2(__float2bfloat16_rn(x0 - __bfloat162float(h0)),
                 __float2bfloat16_rn(x1 - __bfloat162float(h1)));
    return bf2(h0, h1);
}

// ---------------- kernel 0: weight prep (tc path) ----------------
__global__ void __launch_bounds__(512, 1)
wn_prep(const float* __restrict__ wf, const float* __restrict__ wg,
        const float* __restrict__ wr, const float* __restrict__ ws) {
    int L = blockIdx.x;
    int tid = threadIdx.x;
    unsigned char* d0 = g_wfgp + (size_t)L * 65536;
#pragma unroll
    for (int it = 0; it < 8; ++it) {
        int v = tid + 512 * it;               // 0..4095
        int c2 = v >> 5, cp = v & 31;
        const float* src = (c2 < 64) ? (wf + (size_t)L * 8192 + c2 * 128 + cp * 4)
                                     : (wg + (size_t)L * 8192 + (c2 - 64) * 128 + cp * 4);
        float4 wv = *(const float4*)src;      // {cin0 tap0, cin0 tap1, cin1 tap0, cin1 tap1}
        unsigned off = (unsigned)(c2 * 128 + cp * 4);
        unsigned sw = off ^ ((off >> 3) & 0x70);
        unsigned lo, hi;
        hi = hi_lo_pack(wv.x, wv.z, lo);      // tap0 (prev)
        *(unsigned*)(d0 + sw)         = hi;
        *(unsigned*)(d0 + 16384 + sw) = lo;
        hi = hi_lo_pack(wv.y, wv.w, lo);      // tap1 (cur)
        *(unsigned*)(d0 + 32768 + sw) = hi;
        *(unsigned*)(d0 + 49152 + sw) = lo;
    }
    unsigned char* d1 = g_wrp + (size_t)L * 16384;
#pragma unroll
    for (int it = 0; it < 4; ++it) {
        int v = tid + 512 * it;               // 0..2047
        int c = v >> 5, cp = v & 31;
        float2 wv = *(const float2*)(wr + (size_t)L * 4096 + c * 64 + cp * 2);
        unsigned off = (unsigned)(c * 128 + cp * 4);
        unsigned sw = off ^ ((off >> 3) & 0x70);
        unsigned lo, hi;
        hi = hi_lo_pack(wv.x, wv.y, lo);
        *(unsigned*)(d1 + sw)        = hi;
        *(unsigned*)(d1 + 8192 + sw) = lo;
    }
    unsigned char* d2 = g_wsp + (size_t)L * 65536;
#pragma unroll
    for (int it = 0; it < 8; ++it) {
        int v = tid + 512 * it;               // 0..4095
        int row = v >> 4, c4 = v & 15;
        float4 wv = *(const float4*)(ws + (size_t)L * (CS_ * CR_) + row * 64 + c4 * 4);
        int q = row >> 7, c = row & 127;
        unsigned lo0, hi0, lo1, hi1;
        hi0 = hi_lo_pack(wv.x, wv.y, lo0);
        hi1 = hi_lo_pack(wv.z, wv.w, lo1);
        unsigned off = (unsigned)(c * 128 + c4 * 8);
        unsigned sw = off ^ ((off >> 3) & 0x70);
        unsigned char* base = d2 + q * 32768;
        *(u64*)(base + sw)         = (u64)hi0 | ((u64)hi1 << 32);
        *(u64*)(base + 16384 + sw) = (u64)lo0 | ((u64)lo1 << 32);
    }
}

// ---------------- kernel 1: input 1x1 conv ([b][c][t]) ----------------
__global__ void wn_input(const float* __restrict__ x,
                         const float* __restrict__ w,
                         const float* __restrict__ bias) {
    __shared__ float sw[CR_ * CIN_];
    __shared__ float sb[CR_];
    int tid = threadIdx.x;
    for (int k = tid; k < CR_ * CIN_; k += 256) sw[k] = w[k];
    if (tid < CR_) sb[tid] = bias[tid];
    __syncthreads();
    int gt = blockIdx.x * 256 + tid;
    int b = gt >> 12;
    int t = gt & (T_ - 1);
    float xv[CIN_];
#pragma unroll
    for (int ci = 0; ci < CIN_; ++ci) xv[ci] = x[(b * CIN_ + ci) * T_ + t];
#pragma unroll 4
    for (int c = 0; c < CR_; ++c) {
        float a = sb[c];
#pragma unroll
        for (int ci = 0; ci < CIN_; ++ci) a = fmaf(sw[c * CIN_ + ci], xv[ci], a);
        g_h0[(b * CR_ + c) * T_ + t] = a;
    }
}

// ---------------- kernel 2a: scalar WaveNet layer (fallback) ----------------
#define SMEM_L ((16384 + 16384 + 16384 + 4096) * 4)

__global__ void __launch_bounds__(512, 1)
wn_layer(const float* __restrict__ wf, const float* __restrict__ bf,
         const float* __restrict__ wg, const float* __restrict__ bg,
         const float* __restrict__ wr, const float* __restrict__ br,
         int layer, int dil, int flip) {
    extern __shared__ float sm[];
    float* s_cur  = sm;
    float* s_prev = sm + 16384;
    float* s_wfg  = sm + 32768;
    float* s_wr   = sm + 49152;

    const float* hin  = flip ? g_h1 : g_h0;
    float*       hout = flip ? g_h0 : g_h1;

    int tid = threadIdx.x;
    int b   = blockIdx.x >> 4;
    int tt0 = (blockIdx.x & 15) * TT_;
    const float* hb = hin + (size_t)b * CR_ * T_;

    for (int idx = tid; idx < 8192; idx += 512) {
        int c = idx >> 7, r = idx & 127, cin = r >> 1, tap = r & 1;
        int o = cin * 256 + tap * 128 + c;
        s_wfg[o]      = wf[idx];
        s_wfg[o + 64] = wg[idx];
    }
    for (int idx = tid; idx < 4096; idx += 512)
        s_wr[(idx & 63) * 64 + (idx >> 6)] = wr[idx];

    for (int k = tid; k < 4096; k += 512) {
        int row = k >> 6, col = (k & 63) << 2;
        *(float4*)(s_cur + row * 256 + col) =
            *(const float4*)(hb + row * T_ + tt0 + col);
    }
    for (int k = tid; k < 16384; k += 512) {
        int row = k >> 8, j = k & 255;
        int tp = tt0 - dil + j;
        s_prev[row * 256 + j] = (tp >= 0) ? hb[row * T_ + tp] : 0.f;
    }
    __syncthreads();

    int w = tid >> 5, l = tid & 31;
    int cb = w * 4;
    int j0 = 2 * l;

    u64 accF[4][4], accG[4][4];
#pragma unroll
    for (int k = 0; k < 4; ++k) {
        u64 bF = dup2(__ldg(bf + cb + k));
        u64 bG = dup2(__ldg(bg + cb + k));
#pragma unroll
        for (int p = 0; p < 4; ++p) { accF[k][p] = bF; accG[k][p] = bG; }
    }

    const float* curp = s_cur  + j0;
    const float* prvp = s_prev + j0;

#pragma unroll 4
    for (int cin = 0; cin < 64; ++cin) {
        u64 hc[4], hp[4];
#pragma unroll
        for (int p = 0; p < 4; ++p) {
            hc[p] = ld64s(curp + cin * 256 + 64 * p);
            hp[p] = ld64s(prvp + cin * 256 + 64 * p);
        }
        const float* wp = s_wfg + cin * 256 + cb;
        float F0[4], G0[4], F1[4], G1[4];
        *(float4*)F0 = *(const float4*)(wp);
        *(float4*)G0 = *(const float4*)(wp + 64);
        *(float4*)F1 = *(const float4*)(wp + 128);
        *(float4*)G1 = *(const float4*)(wp + 192);
#pragma unroll
        for (int k = 0; k < 4; ++k) {
            u64 wf0 = dup2(F0[k]), wf1 = dup2(F1[k]);
            u64 wg0 = dup2(G0[k]), wg1 = dup2(G1[k]);
#pragma unroll
            for (int p = 0; p < 4; ++p) {
                accF[k][p] = fma2(wf0, hp[p], accF[k][p]);
                accF[k][p] = fma2(wf1, hc[p], accF[k][p]);
                accG[k][p] = fma2(wg0, hp[p], accG[k][p]);
                accG[k][p] = fma2(wg1, hc[p], accG[k][p]);
            }
        }
    }

    u64 zr[4][4];
    float* zb = g_z + (size_t)layer * HSZ + (size_t)b * CR_ * T_ + tt0;
#pragma unroll
    for (int k = 0; k < 4; ++k)
#pragma unroll
        for (int p = 0; p < 4; ++p) {
            float2 fv = unpk2(accF[k][p]);
            float2 gv = unpk2(accG[k][p]);
            float z0 = tanhf_(fv.x) * sigf(gv.x);
            float z1 = tanhf_(fv.y) * sigf(gv.y);
            u64 zz = pack2(z0, z1);
            zr[k][p] = zz;
            st64(zb + (cb + k) * T_ + j0 + 64 * p, zz);
        }

    __syncthreads();
#pragma unroll
    for (int k = 0; k < 4; ++k)
#pragma unroll
        for (int p = 0; p < 4; ++p)
            st64(s_prev + (cb + k) * 256 + j0 + 64 * p, zr[k][p]);
    __syncthreads();

    u64 accR[4][4];
#pragma unroll
    for (int k = 0; k < 4; ++k) {
        u64 bR = dup2(__ldg(br + cb + k));
#pragma unroll
        for (int p = 0; p < 4; ++p) accR[k][p] = bR;
    }
#pragma unroll 4
    for (int cin = 0; cin < 64; ++cin) {
        u64 zc[4];
#pragma unroll
        for (int p = 0; p < 4; ++p) zc[p] = ld64s(prvp + cin * 256 + 64 * p);
        float R[4];
        *(float4*)R = *(const float4*)(s_wr + cin * 64 + cb);
#pragma unroll
        for (int k = 0; k < 4; ++k) {
            u64 wk = dup2(R[k]);
#pragma unroll
            for (int p = 0; p < 4; ++p) accR[k][p] = fma2(wk, zc[p], accR[k][p]);
        }
    }
    float* ho = hout + (size_t)b * CR_ * T_ + tt0;
#pragma unroll
    for (int k = 0; k < 4; ++k)
#pragma unroll
        for (int p = 0; p < 4; ++p) {
            u64 hv = ld64s(s_cur + (cb + k) * 256 + j0 + 64 * p);
            st64(ho + (cb + k) * T_ + j0 + 64 * p, add2(accR[k][p], hv));
        }
}

// ---------------- kernel 2b: persistent tcgen05 layer, TMEM ping-pong ----------------
// Two 128-col regions R0=0, R1=128. Tile j (p=j&1): A(j)@R[p], D1(j)@R[1-p];
// after MMA1 wait + z-epilogue LDTM, z(j)->R[p]+0..63, D2(j)->R[p]+64..127,
// and A(j+1) is staged into R[1-p] under MMA2(j)'s shadow.
// smem: [256..1024) biases | Wfg 64KB | Wr 16KB | z-image scratch 16KB
#define SB_BIAS 256
#define WP3_H 1024
#define WP3_L 17408
#define WC3_H 33792
#define WC3_L 50176
#define WR3_H 66560
#define WR3_L 74752
#define ZIMG  82944
#define SMEM_LT3 99328

#define ID1 0x8200490u   // f32 acc | bf16 | N=128 | M=128
#define ID2 0x8100490u   // f32 acc | bf16 | N=64  | M=128

__global__ void __launch_bounds__(512, 2)
wn_layer_tc(const float* __restrict__ bf, const float* __restrict__ bg,
            const float* __restrict__ br,
            int layer, int dil, int flip) {
#if HAS_TC
    extern __shared__ char smc[];
    uint32_t sb = smem_u32(smc);
    int tid = threadIdx.x, wid = tid >> 5, lane = tid & 31;
    int sub = wid & 3;                // TMEM subpartition
    int cg  = wid >> 2;               // cin/col group (0..3)
    int gt0 = blockIdx.x * NTPC;      // first tile (4 consecutive, same b)
    int b   = gt0 >> 5;
    int tl  = sub * 32 + lane;        // local t (0..127)
    const float* hin = flip ? g_h1 : g_h0;
    float* hout = flip ? g_h0 : g_h1;
    const float* hb = hin + (size_t)b * CR_ * T_;
    float* hob = hout + (size_t)b * CR_ * T_;
    uint32_t wo = ((uint32_t)sub << 21) + (uint32_t)(cg * 8);

    if (wid == 0) TC_ALLOC(sb, 256);
    if (tid == 0) { MBAR_INIT(sb + 8, 1); MBAR_INIT(sb + 16, 1); }
    __syncthreads();
    uint32_t tmem;
    asm volatile("ld.shared.b32 %0, [%1];" : "=r"(tmem) : "r"(sb));
    if (wid == 0) TC_RELINQ();

    // ---- stage biases + weights ONCE ----
    {
        float* sbias = (float*)(smc + SB_BIAS);
        if (tid < 64)        sbias[tid] = __ldg(bf + tid);
        else if (tid < 128)  sbias[tid] = __ldg(bg + tid - 64);
        else if (tid < 192)  sbias[tid] = __ldg(br + tid - 128);

        const uint4* wsrc = (const uint4*)(g_wfgp + (size_t)layer * 65536);
        uint4* wdst = (uint4*)(smc + WP3_H);
#pragma unroll
        for (int it = 0; it < 8; ++it) {
            int idx = tid + 512 * it;          // 0..4095
            wdst[idx] = wsrc[idx];
        }
        const uint4* rsrc = (const uint4*)(g_wrp + (size_t)layer * 16384);
        uint4* rdst = (uint4*)(smc + WR3_H);
#pragma unroll
        for (int it = 0; it < 2; ++it) {
            int idx = tid + 512 * it;          // 0..1023
            rdst[idx] = rsrc[idx];
        }
    }

    // ---- prologue: stage A(tile 0) into region 0 ----
    {
        int tg = ((gt0 & 31) * TTL) + tl;
        unsigned cur_h[8], cur_l[8], prv_h[8], prv_l[8];
        bool pv = (tg - dil) >= 0;
#pragma unroll
        for (int k = 0; k < 8; ++k) {
            int cin = 16 * cg + 2 * k;
            const float* p0 = hb + (size_t)cin * T_;
            const float* p1p = p0 + T_;
            cur_h[k] = hi_lo_pack(p0[tg], p1p[tg], cur_l[k]);
            float a0 = 0.f, a1 = 0.f;
            if (pv) { a0 = p0[tg - dil]; a1 = p1p[tg - dil]; }
            prv_h[k] = hi_lo_pack(a0, a1, prv_l[k]);
        }
        TC_ST8(tmem + 0  + wo, prv_h);
        TC_ST8(tmem + 32 + wo, cur_h);
        TC_ST8(tmem + 64 + wo, prv_l);
        TC_ST8(tmem + 96 + wo, cur_l);
        TC_WAIT_ST();
    }
    TC_FENCE_BEFORE();
    FENCE_ASYNC();
    __syncthreads();

    int p1 = 0, p2 = 0;
    for (int j = 0; j < NTPC; ++j) {
        int gt  = gt0 + j;
        int tg  = ((gt & 31) * TTL) + tl;
        uint32_t ra = tmem + ((j & 1) ? 128u : 0u);   // A / z / D2 region
        uint32_t rd = tmem + ((j & 1) ? 0u : 128u);   // D1 / next-A region

        // ---- MMA1 (TS): 24 dispatches; A@ra, D1@rd ----
        if (wid == 0 && elect1()) {
            TC_FENCE_AFTER();
            uint64_t wph = MK_DESC(sb + WP3_H), wpl = MK_DESC(sb + WP3_L);
            uint64_t wch = MK_DESC(sb + WC3_H), wcl = MK_DESC(sb + WC3_L);
#pragma unroll
            for (int k = 0; k < 4; ++k)
                mma_f16_ts(rd, ra + 0  + k * 8, wph + 2 * k, ID1, k > 0 ? 1u : 0u);
#pragma unroll
            for (int k = 0; k < 4; ++k)
                mma_f16_ts(rd, ra + 32 + k * 8, wch + 2 * k, ID1, 1u);
#pragma unroll
            for (int k = 0; k < 4; ++k)
                mma_f16_ts(rd, ra + 0  + k * 8, wpl + 2 * k, ID1, 1u);
#pragma unroll
            for (int k = 0; k < 4; ++k)
                mma_f16_ts(rd, ra + 32 + k * 8, wcl + 2 * k, ID1, 1u);
#pragma unroll
            for (int k = 0; k < 4; ++k)
                mma_f16_ts(rd, ra + 64 + k * 8, wph + 2 * k, ID1, 1u);
#pragma unroll
            for (int k = 0; k < 4; ++k)
                mma_f16_ts(rd, ra + 96 + k * 8, wch + 2 * k, ID1, 1u);
            TC_COMMIT(sb + 8);
        }
        MBAR_WAIT(sb + 8, p1);
        p1 ^= 1;
        TC_FENCE_AFTER();

        // ---- z epilogue: LDTM D1@rd; z -> ra+0/32; hi-image into scratch ----
        unsigned zl[8];
        {
            const float* sbias = (const float*)(smc + SB_BIAS);
            uint32_t fr[16], gr[16];
            LDTM_X16(fr, rd + 16 * cg);
            LDTM_X16(gr, rd + 64 + 16 * cg);
            TC_WAIT_LD();
            unsigned zh[8];
#pragma unroll
            for (int jj = 0; jj < 8; ++jj) {
                int c0 = 16 * cg + 2 * jj;
                float F0 = __uint_as_float(fr[2 * jj])     + sbias[c0];
                float G0 = __uint_as_float(gr[2 * jj])     + sbias[64 + c0];
                float F1 = __uint_as_float(fr[2 * jj + 1]) + sbias[c0 + 1];
                float G1 = __uint_as_float(gr[2 * jj + 1]) + sbias[64 + c0 + 1];
                zh[jj] = hi_lo_pack(gated(F0, G0), gated(F1, G1), zl[jj]);
            }
            TC_ST8(ra + 0  + wo, zh);
            TC_ST8(ra + 32 + wo, zl);
            TC_WAIT_ST();
            unsigned tx = (unsigned)((tl & 7) * 16);
            unsigned b0 = (unsigned)(cg * 32);
            char* ip = smc + ZIMG + tl * 128;
            *(uint4*)(ip + (b0 ^ tx))        = make_uint4(zh[0], zh[1], zh[2], zh[3]);
            *(uint4*)(ip + ((b0 + 16) ^ tx)) = make_uint4(zh[4], zh[5], zh[6], zh[7]);
        }
        TC_FENCE_BEFORE();
        __syncthreads();   // z in TMEM visible; D1 region (rd) now dead

        // ---- MMA2 (TS): z@ra+0/32 -> D2@ra+64 ----
        if (wid == 0 && elect1()) {
            TC_FENCE_AFTER();
            uint64_t rh = MK_DESC(sb + WR3_H), rl = MK_DESC(sb + WR3_L);
#pragma unroll
            for (int k = 0; k < 4; ++k)
                mma_f16_ts(ra + 64, ra + 0  + k * 8, rh + 2 * k, ID2, k > 0 ? 1u : 0u);
#pragma unroll
            for (int k = 0; k < 4; ++k)
                mma_f16_ts(ra + 64, ra + 0  + k * 8, rl + 2 * k, ID2, 1u);
#pragma unroll
            for (int k = 0; k < 4; ++k)
                mma_f16_ts(ra + 64, ra + 32 + k * 8, rh + 2 * k, ID2, 1u);
            TC_COMMIT(sb + 16);
        }

        // ---- overlap with MMA2: stage A(j+1) into rd region ----
        if (j + 1 < NTPC) {
            int tgn = (((gt + 1) & 31) * TTL) + tl;
            unsigned cur_h[8], cur_l[8], prv_h[8], prv_l[8];
            bool pv = (tgn - dil) >= 0;
#pragma unroll
            for (int k = 0; k < 8; ++k) {
                int cin = 16 * cg + 2 * k;
                const float* p0 = hb + (size_t)cin * T_;
                const float* p1p = p0 + T_;
                cur_h[k] = hi_lo_pack(p0[tgn], p1p[tgn], cur_l[k]);
                float a0 = 0.f, a1 = 0.f;
                if (pv) { a0 = p0[tgn - dil]; a1 = p1p[tgn - dil]; }
                prv_h[k] = hi_lo_pack(a0, a1, prv_l[k]);
            }
            TC_ST8(rd + 0  + wo, prv_h);
            TC_ST8(rd + 32 + wo, cur_h);
            TC_ST8(rd + 64 + wo, prv_l);
            TC_ST8(rd + 96 + wo, cur_l);
            TC_WAIT_ST();
        }

        // ---- prefetch residual h (overlap with MMA2) ----
        float hc[16];
#pragma unroll
        for (int k = 0; k < 16; ++k)
            hc[k] = hb[(size_t)(16 * cg + k) * T_ + tg];

        // ---- copy hi image -> g_zsw (overlap with MMA2) ----
        unsigned char* img = g_zsw + ((size_t)layer * 512 + (gt >> 1)) * 65536;
        {
            const uint4* sh = (const uint4*)(smc + ZIMG);
            uint4* dh = (uint4*)img + ((gt & 1) << 10);
#pragma unroll
            for (int j2 = 0; j2 < 2; ++j2)
                dh[tid + 512 * j2] = sh[tid + 512 * j2];
        }
        __syncthreads();   // scratch fully copied out

        // ---- lo image into scratch, then copy out ----
        {
            unsigned tx = (unsigned)((tl & 7) * 16);
            unsigned b0 = (unsigned)(cg * 32);
            char* ip = smc + ZIMG + tl * 128;
            *(uint4*)(ip + (b0 ^ tx))        = make_uint4(zl[0], zl[1], zl[2], zl[3]);
            *(uint4*)(ip + ((b0 + 16) ^ tx)) = make_uint4(zl[4], zl[5], zl[6], zl[7]);
        }
        __syncthreads();
        {
            const uint4* sl = (const uint4*)(smc + ZIMG);
            uint4* dl = (uint4*)(img + 32768) + ((gt & 1) << 10);
#pragma unroll
            for (int j2 = 0; j2 < 2; ++j2)
                dl[tid + 512 * j2] = sl[tid + 512 * j2];
        }

        MBAR_WAIT(sb + 16, p2);
        p2 ^= 1;
        TC_FENCE_AFTER();

        // ---- residual epilogue: LDTM D2@ra+64 ----
        {
            const float* sbias = (const float*)(smc + SB_BIAS);
            uint32_t rr[16];
            LDTM_X16(rr, ra + 64 + 16 * cg);
            TC_WAIT_LD();
#pragma unroll
            for (int k = 0; k < 16; ++k) {
                int c = 16 * cg + k;
                hob[(size_t)c * T_ + tg] =
                    __uint_as_float(rr[k]) + sbias[128 + c] + hc[k];
            }
        }
        TC_FENCE_BEFORE();
        __syncthreads();   // A(j+1) STTM + TMEM reads complete before next MMA1
    }
    if (wid == 0) TC_DEALLOC(tmem, 256);
#else
    volatile __shared__ int s_marker[8];
    s_marker[threadIdx.x & 7] = (int)threadIdx.x;
    if (s_marker[0] == -12345) g_h0[0] = bf[0] + bg[0] + br[0];
#endif
}

// ---------------- kernel 3a: scalar skip reduction (fallback) ----------------
#define SMEM_S ((16384 + 8192) * 4)

__global__ void __launch_bounds__(512, 1)
wn_skip(const float* __restrict__ ws, const float* __restrict__ bs,
        float* __restrict__ out) {
    extern __shared__ float sm[];
    float* s_z = sm;
    float* s_w = sm + 16384;

    int tid = threadIdx.x;
    int b   = blockIdx.x >> 4;
    int tt0 = (blockIdx.x & 15) * TT_;
    int w = tid >> 5, l = tid & 31;
    int j0 = 2 * l;

    for (int q = 0; q < 2; ++q) {
        int cq = q * 128 + w * 8;
        u64 acc[8][4];
#pragma unroll
        for (int k = 0; k < 8; ++k) {
            float s = 0.f;
            for (int i = 0; i < L_; ++i) s += __ldg(bs + i * CS_ + cq + k);
            u64 d = dup2(s);
#pragma unroll
            for (int p = 0; p < 4; ++p) acc[k][p] = d;
        }
        for (int i = 0; i < L_; ++i) {
            __syncthreads();
            const float* zsrc = g_z + (size_t)i * HSZ + (size_t)b * CR_ * T_ + tt0;
            for (int k = tid; k < 4096; k += 512) {
                int row = k >> 6, col = (k & 63) << 2;
                *(float4*)(s_z + row * 256 + col) =
                    *(const float4*)(zsrc + row * T_ + col);
            }
            const float* wsrc = ws + i * (CS_ * CR_) + q * 128 * 64;
            for (int k2 = tid; k2 < 8192; k2 += 512) {
                int c = k2 >> 6, cin = k2 & 63;
                s_w[cin * 128 + c] = wsrc[k2];
            }
            __syncthreads();
            const float* zp = s_z + j0;
#pragma unroll 4
            for (int cin = 0; cin < 64; ++cin) {
                u64 zc[4];
#pragma unroll
                for (int p = 0; p < 4; ++p) zc[p] = ld64s(zp + cin * 256 + 64 * p);
                float Wv[8];
                *(float4*)(Wv)     = *(const float4*)(s_w + cin * 128 + w * 8);
                *(float4*)(Wv + 4) = *(const float4*)(s_w + cin * 128 + w * 8 + 4);
#pragma unroll
                for (int k = 0; k < 8; ++k) {
                    u64 wk = dup2(Wv[k]);
#pragma unroll
                    for (int p = 0; p < 4; ++p) acc[k][p] = fma2(wk, zc[p], acc[k][p]);
                }
            }
        }
        float* ob = out + (size_t)b * CS_ * T_ + tt0;
#pragma unroll
        for (int k = 0; k < 8; ++k)
#pragma unroll
            for (int p = 0; p < 4; ++p)
                st64(ob + (cq + k) * T_ + j0 + 64 * p, acc[k][p]);
    }
}

// ---------------- kernel 3b: tcgen05 skip reduction (pure-copy dbuf) ----------------
#define SK_B0H 1024
#define SK_B0L 33792
#define SK_B1H 66560
#define SK_B1L 99328
#define SK_A   132096          // Ah0 | Al0 | Ah1 | Al1 (16 KB each)
#define SK_SMEM (SK_A + 65536 + 64)

#define SK_IDESC 0x8400490u   // f32 acc | bf16 a,b | N=256 | M=128

__global__ void __launch_bounds__(512, 1)
wn_skip_tc(const float* __restrict__ bs, float* __restrict__ out) {
#if HAS_TC
    extern __shared__ char smc[];
    uint32_t sb = smem_u32(smc);

    int tid  = threadIdx.x;
    int wid  = tid >> 5;
    int lane = tid & 31;
    int b    = blockIdx.x >> 4;
    int tt0  = (blockIdx.x & 15) * TT_;

    if (wid == 0) TC_ALLOC(sb, 512);
    if (tid == 0) MBAR_INIT(sb + 8, 1);
    __syncthreads();
    uint32_t tmem;
    asm volatile("ld.shared.b32 %0, [%1];" : "=r"(tmem) : "r"(sb));
    if (wid == 0) TC_RELINQ();

    // prologue: copy z(0) tile image into buffer 0 (pure uint4 copies)
    {
        const uint4* src = (const uint4*)(g_zsw + ((size_t)0 * 512 + blockIdx.x) * 65536);
#pragma unroll
        for (int k2 = tid; k2 < 2048; k2 += 512) {
            ((uint4*)(smc + SK_B0H))[k2] = src[k2];
            ((uint4*)(smc + SK_B0L))[k2] = src[k2 + 2048];
        }
    }

    int ph = 0;
    for (int i = 0; i < L_; ++i) {
        int buf = i & 1;
        if (i > 0) { MBAR_WAIT(sb + 8, ph); ph ^= 1; }   // MMA(i-1) done

        // ---- stage A: pure copy of pre-converted ws images ----
        {
            const uint4* asrc = (const uint4*)(g_wsp + (size_t)i * 65536);
            uint4* adst = (uint4*)(smc + SK_A);
#pragma unroll
            for (int it = 0; it < 8; ++it) {
                int idx = tid + 512 * it;      // 0..4095
                adst[idx] = asrc[idx];
            }
        }

        FENCE_ASYNC();
        __syncthreads();

        if (wid == 0 && elect1()) {
            uint64_t bdh = MK_DESC(sb + (buf ? SK_B1H : SK_B0H));
            uint64_t bdl = MK_DESC(sb + (buf ? SK_B1L : SK_B0L));
#pragma unroll
            for (int q = 0; q < 2; ++q) {
                uint64_t adh = MK_DESC(sb + SK_A + q * 32768);
                uint64_t adl = MK_DESC(sb + SK_A + q * 32768 + 16384);
                uint32_t dt  = tmem + q * 256;
#pragma unroll
                for (int k = 0; k < 4; ++k)
                    mma_f16_ss(dt, adh + 2 * k, bdh + 2 * k, SK_IDESC,
                               (i == 0 && k == 0) ? 0u : 1u);
#pragma unroll
                for (int k = 0; k < 4; ++k)
                    mma_f16_ss(dt, adh + 2 * k, bdl + 2 * k, SK_IDESC, 1u);
#pragma unroll
                for (int k = 0; k < 4; ++k)
                    mma_f16_ss(dt, adl + 2 * k, bdh + 2 * k, SK_IDESC, 1u);
            }
            TC_COMMIT(sb + 8);
        }

        // prefetch z(i+1) into the other buffer while MMA(i) runs
        if (i + 1 < L_) {
            int nb = buf ^ 1;
            const uint4* src = (const uint4*)(g_zsw + ((size_t)(i + 1) * 512 + blockIdx.x) * 65536);
            char* dsth = smc + (nb ? SK_B1H : SK_B0H);
            char* dstl = smc + (nb ? SK_B1L : SK_B0L);
#pragma unroll
            for (int k2 = tid; k2 < 2048; k2 += 512) {
                ((uint4*)dsth)[k2] = src[k2];
                ((uint4*)dstl)[k2] = src[k2 + 2048];
            }
        }
    }

    MBAR_WAIT(sb + 8, ph);
    TC_FENCE_AFTER();

    // epilogue: 16 warps; sub = lane-group, cq = 64-col chunk
    int sub = wid & 3;
    int cq  = wid >> 2;          // 0..3
#pragma unroll
    for (int q = 0; q < 2; ++q) {
        int c = q * 128 + sub * 32 + lane;
        float bsum = 0.f;
#pragma unroll
        for (int i = 0; i < L_; ++i) bsum += __ldg(bs + i * CS_ + c);
        float* op = out + (size_t)b * CS_ * T_ + (size_t)c * T_ + tt0 + cq * 64;
#pragma unroll
        for (int uu = 0; uu < 2; ++uu) {
            uint32_t dr[32];
            LDTM_X32(dr, tmem + q * 256 + cq * 64 + uu * 32);
            TC_WAIT_LD();
            float4 o4;
#pragma unroll
            for (int jj = 0; jj < 8; ++jj) {
                o4.x = __uint_as_float(dr[4 * jj + 0]) + bsum;
                o4.y = __uint_as_float(dr[4 * jj + 1]) + bsum;
                o4.z = __uint_as_float(dr[4 * jj + 2]) + bsum;
                o4.w = __uint_as_float(dr[4 * jj + 3]) + bsum;
                *(float4*)(op + uu * 32 + 4 * jj) = o4;
            }
        }
    }

    __syncthreads();
    if (wid == 0) TC_DEALLOC(tmem, 512);
#else
    volatile __shared__ int s_marker[8];
    s_marker[threadIdx.x & 7] = (int)threadIdx.x;
    if (s_marker[0] == -12345) out[0] = bs[0];
#endif
}

// ---------------- launch ----------------
extern "C" void kernel_launch(void* const* d_in, const int* in_sizes, int n_in,
                              void* d_out, int out_size) {
    const float* x    = (const float*)d_in[0];
    const float* w_in = (const float*)d_in[1];
    const float* b_in = (const float*)d_in[2];
    const float* w_f  = (const float*)d_in[3];
    const float* b_f  = (const float*)d_in[4];
    const float* w_g  = (const float*)d_in[5];
    const float* b_g  = (const float*)d_in[6];
    const float* w_s  = (const float*)d_in[7];
    const float* b_s  = (const float*)d_in[8];
    const float* w_r  = (const float*)d_in[9];
    const float* b_r  = (const float*)d_in[10];

    cudaFuncSetAttribute(wn_layer,    cudaFuncAttributeMaxDynamicSharedMemorySize, SMEM_L);
    cudaFuncSetAttribute(wn_layer_tc, cudaFuncAttributeMaxDynamicSharedMemorySize, SMEM_LT3);
    cudaFuncSetAttribute(wn_skip,     cudaFuncAttributeMaxDynamicSharedMemorySize, SMEM_S);
    cudaFuncSetAttribute(wn_skip_tc,  cudaFuncAttributeMaxDynamicSharedMemorySize, SK_SMEM);

    cudaFuncAttributes fa;
    bool use_tc = false;
    if (cudaFuncGetAttributes(&fa, wn_skip_tc) == cudaSuccess)
        use_tc = (fa.sharedSizeBytes == 0);
    if (use_tc) {
        if (cudaFuncGetAttributes(&fa, wn_layer_tc) != cudaSuccess ||
            fa.sharedSizeBytes != 0)
            use_tc = false;
    }

    if (use_tc)
        wn_prep<<<L_, 512>>>(w_f, w_g, w_r, w_s);

    wn_input<<<(B_ * T_) / 256, 256>>>(x, w_in, b_in);

    for (int i = 0; i < L_; ++i) {
        int d = 1 << (i % 10);
        if (use_tc)
            wn_layer_tc<<<B_ * (T_ / TTL) / NTPC, 512, SMEM_LT3>>>(
                b_f + i * CR_, b_g + i * CR_, b_r + i * CR_, i, d, i & 1);
        else
            wn_layer<<<B_ * (T_ / TT_), 512, SMEM_L>>>(
                w_f + (size_t)i * CR_ * CR_ * 2, b_f + i * CR_,
                w_g + (size_t)i * CR_ * CR_ * 2, b_g + i * CR_,
                w_r + (size_t)i * CR_ * CR_,     b_r + i * CR_,
                i, d, i & 1);
    }

    if (use_tc)
        wn_skip_tc<<<B_ * (T_ / TT_), 512, SK_SMEM>>>(b_s, (float*)d_out);
    else
        wn_skip<<<B_ * (T_ / TT_), 512, SMEM_S>>>(w_s, b_s, (float*)d_out);
}